// round 5
// baseline (speedup 1.0000x reference)
#include <cuda_runtime.h>
#include <cstdint>

#define PNUM 128
#define MAXBATCH 8192
#define NB 4
#define MAXBLOCKS (MAXBATCH / NB)

typedef unsigned long long u64;

__device__ float g_block_loss[MAXBLOCKS];
__device__ int   g_count;  // zero-init at load; reset by last block each call

// ---- packed f32x2 helpers (sm_103a) ----
__device__ __forceinline__ u64 pk_fma(u64 a, u64 b, u64 c) {
    u64 r;
    asm("fma.rn.f32x2 %0, %1, %2, %3;" : "=l"(r) : "l"(a), "l"(b), "l"(c));
    return r;
}
__device__ __forceinline__ u64 pk_pack(float lo, float hi) {
    u64 r;
    asm("mov.b64 %0, {%1, %2};" : "=l"(r) : "f"(lo), "f"(hi));
    return r;
}
__device__ __forceinline__ void pk_unpack(u64 v, float& lo, float& hi) {
    asm("mov.b64 {%0, %1}, %2;" : "=f"(lo), "=f"(hi) : "l"(v));
}

#define ONE2 0x3F8000003F800000ULL          // packed (1.0f, 1.0f)
#define NEGMASK 0x8000000080000000ULL       // sign bits of both packed floats

// smoothL1(d) = 0.5*d^2 - 0.5*m^2 + m - 0.5,  m = max(|d|, 1)
// fma pipe: FFMA2 x4; alu pipe: FMNMX x2 (abs = free src modifier)
__device__ __forceinline__ void evalpair(u64 p, u64 ng, u64& sQ, u64& sM2, u64& sM) {
    u64 d = pk_fma(ng, ONE2, p);        // d = p - g
    sQ = pk_fma(d, d, sQ);
    float dx, dy;
    pk_unpack(d, dx, dy);
    float mx = fmaxf(fabsf(dx), 1.0f);  // FMNMX (alu)
    float my = fmaxf(fabsf(dy), 1.0f);
    u64 m = pk_pack(mx, my);
    sM2 = pk_fma(m, m, sM2);
    sM  = pk_fma(m, ONE2, sM);
}

__global__ __launch_bounds__(PNUM)
void match_kernel(const float* __restrict__ pred0,
                  const float* __restrict__ pred1,
                  const float* __restrict__ gt,
                  float* __restrict__ out,
                  int nbatch, int nblocks) {
    __shared__ __align__(16) u64 sp0[PNUM];
    __shared__ __align__(16) u64 sp1[PNUM];
    // Negated gt, duplicated for the cyclic shift. sngB is the same ring
    // advanced by one point so odd-shift threads get a 16B-aligned base and
    // can fetch 2 gt points per LDS.128.
    __shared__ __align__(16) u64 sngA[2 * PNUM];
    __shared__ __align__(16) u64 sngB[2 * PNUM];
    __shared__ float redA[4], redB[4];
    __shared__ int s_last;

    const int tid = threadIdx.x;
    const int blk = blockIdx.x;
    const int b0 = blk * NB;

    int nb_local = nbatch - b0;
    if (nb_local > NB) nb_local = NB;

    // Prefetch batch b0 into registers.
    u64 rp0 = 0, rp1 = 0, rg = 0;
    if (nb_local > 0) {
        const int g0 = b0 * PNUM + tid;
        rp0 = reinterpret_cast<const u64*>(pred0)[g0];
        rp1 = reinterpret_cast<const u64*>(pred1)[g0];
        rg  = reinterpret_cast<const u64*>(gt)[g0];
    }

    float blocksum = 0.0f;

    for (int t = 0; t < nb_local; t++) {
        // Publish current batch to smem.
        sp0[tid] = rp0;
        sp1[tid] = rp1;
        {
            u64 ngu = rg ^ NEGMASK;                 // negate both coords (LOP3)
            sngA[tid] = ngu;
            sngA[tid + PNUM] = ngu;
            const int kb = (tid + PNUM - 1) & (PNUM - 1);  // sngB[k] = ng[k+1]
            sngB[kb] = ngu;
            sngB[kb + PNUM] = ngu;
        }
        __syncthreads();

        // Prefetch next batch (latency hides under the mainloop).
        if (t + 1 < nb_local) {
            const int gn = (b0 + t + 1) * PNUM + tid;
            rp0 = reinterpret_cast<const u64*>(pred0)[gn];
            rp1 = reinterpret_cast<const u64*>(pred1)[gn];
            rg  = reinterpret_cast<const u64*>(gt)[gn];
        }

        // Thread tid handles shift j = tid. 16B-aligned gt base via parity copy.
        const u64* gbase = (tid & 1) ? &sngB[tid - 1] : &sngA[tid];
        u64 sQ0 = 0ull, sM20 = 0ull, sM0 = 0ull;
        u64 sQ1 = 0ull, sM21 = 0ull, sM1 = 0ull;

#pragma unroll 16
        for (int i = 0; i < PNUM; i += 2) {
            ulonglong2 P0 = *reinterpret_cast<const ulonglong2*>(&sp0[i]);   // LDS.128 bcast
            ulonglong2 P1 = *reinterpret_cast<const ulonglong2*>(&sp1[i]);   // LDS.128 bcast
            ulonglong2 G  = *reinterpret_cast<const ulonglong2*>(&gbase[i]); // LDS.128
            evalpair(P0.x, G.x, sQ0, sM20, sM0);
            evalpair(P0.y, G.y, sQ0, sM20, sM0);
            evalpair(P1.x, G.x, sQ1, sM21, sM1);
            evalpair(P1.y, G.y, sQ1, sM21, sM1);
        }

        // constant term: 256 pair-terms * (-0.5) = -128 per shift
        float qx, qy, m2x, m2y, mx, my;
        pk_unpack(sQ0, qx, qy);
        pk_unpack(sM20, m2x, m2y);
        pk_unpack(sM0, mx, my);
        float dis0 = (0.5f * ((qx + qy) - (m2x + m2y)) + (mx + my) - 128.0f) * (1.0f / PNUM);
        pk_unpack(sQ1, qx, qy);
        pk_unpack(sM21, m2x, m2y);
        pk_unpack(sM1, mx, my);
        float dis1 = (0.5f * ((qx + qy) - (m2x + m2y)) + (mx + my) - 128.0f) * (1.0f / PNUM);

#pragma unroll
        for (int o = 16; o > 0; o >>= 1) {
            dis0 = fminf(dis0, __shfl_xor_sync(0xffffffffu, dis0, o));
            dis1 = fminf(dis1, __shfl_xor_sync(0xffffffffu, dis1, o));
        }
        const int w = tid >> 5;
        if ((tid & 31) == 0) {
            redA[w] = dis0;
            redB[w] = dis1;
        }
        __syncthreads();  // also guards smem reuse next iteration
        if (tid == 0) {
            float m0 = fminf(fminf(redA[0], redA[1]), fminf(redA[2], redA[3]));
            float m1 = fminf(fminf(redB[0], redB[1]), fminf(redB[2], redB[3]));
            blocksum += m0 + m1;
        }
    }

    if (tid == 0) {
        g_block_loss[blk] = blocksum;
        __threadfence();
        int v = atomicAdd(&g_count, 1);
        s_last = (v == nblocks - 1) ? 1 : 0;
    }
    __syncthreads();

    // Last finished block reduces all per-block sums (deterministic order).
    if (s_last) {
        __threadfence();
        float acc = 0.0f;
        for (int i = tid; i < nblocks; i += PNUM)
            acc += g_block_loss[i];
#pragma unroll
        for (int o = 16; o > 0; o >>= 1)
            acc += __shfl_xor_sync(0xffffffffu, acc, o);
        const int w = tid >> 5;
        if ((tid & 31) == 0) redA[w] = acc;
        __syncthreads();
        if (tid == 0) {
            float s = (redA[0] + redA[1]) + (redA[2] + redA[3]);
            out[0] = s * (0.5f / (float)nbatch);
            g_count = 0;  // reset for next graph replay
        }
    }
}

extern "C" void kernel_launch(void* const* d_in, const int* in_sizes, int n_in,
                              void* d_out, int out_size) {
    const float* pred0 = (const float*)d_in[0];
    const float* pred1 = (const float*)d_in[1];
    const float* gt    = (const float*)d_in[2];
    int nbatch = in_sizes[0] / (PNUM * 2);
    if (nbatch > MAXBATCH) nbatch = MAXBATCH;
    int nblocks = (nbatch + NB - 1) / NB;

    match_kernel<<<nblocks, PNUM>>>(pred0, pred1, gt, (float*)d_out, nbatch, nblocks);
}

// round 7
// speedup vs baseline: 1.1212x; 1.1212x over previous
#include <cuda_runtime.h>
#include <cstdint>

#define PNUM 128
#define MAXBATCH 8192
#define NB 4
#define MAXBLOCKS ((MAXBATCH + NB - 1) / NB)

typedef unsigned long long u64;

__device__ float g_block_loss[MAXBLOCKS];

// ---- packed f32x2 helpers (sm_103a) ----
__device__ __forceinline__ u64 pk_fma(u64 a, u64 b, u64 c) {
    u64 r;
    asm("fma.rn.f32x2 %0, %1, %2, %3;" : "=l"(r) : "l"(a), "l"(b), "l"(c));
    return r;
}
__device__ __forceinline__ u64 pk_pack(float lo, float hi) {
    u64 r;
    asm("mov.b64 %0, {%1, %2};" : "=l"(r) : "f"(lo), "f"(hi));
    return r;
}
__device__ __forceinline__ void pk_unpack(u64 v, float& lo, float& hi) {
    asm("mov.b64 {%0, %1}, %2;" : "=f"(lo), "=f"(hi) : "l"(v));
}

#define ONE2  0x3F8000003F800000ULL   // packed ( 1.0f,  1.0f)
#define NEG2  0xBF800000BF800000ULL   // packed (-1.0f, -1.0f)

// ---- cp.async helpers ----
__device__ __forceinline__ void cpa8(uint32_t dst, const void* src) {
    asm volatile("cp.async.ca.shared.global [%0], [%1], 8;" :: "r"(dst), "l"(src));
}
__device__ __forceinline__ void cpa_commit() {
    asm volatile("cp.async.commit_group;" ::: "memory");
}
__device__ __forceinline__ void cpa_wait1() {
    asm volatile("cp.async.wait_group 1;" ::: "memory");
}

// smoothL1(d) = 0.5*d^2 - 0.5*m^2 + m - 0.5,  m = max(|d|, 1)
// fma pipe: FFMA2(d = g*-1+p), FFMA2(Q), FFMA2(M2), FFMA2(M += m*1)
// alu pipe: 2x FMNMX (abs = free source modifier)
__device__ __forceinline__ void evalpair(u64 p, u64 g, u64& sQ, u64& sM2, u64& sM) {
    u64 d = pk_fma(g, NEG2, p);         // d = p - g (negation via -1 multiplier)
    sQ = pk_fma(d, d, sQ);
    float dx, dy;
    pk_unpack(d, dx, dy);
    float mx = fmaxf(fabsf(dx), 1.0f);  // FMNMX (alu)
    float my = fmaxf(fabsf(dy), 1.0f);
    u64 m = pk_pack(mx, my);
    sM2 = pk_fma(m, m, sM2);
    sM  = pk_fma(m, ONE2, sM);
}

__global__ __launch_bounds__(PNUM)
void match_kernel(const float* __restrict__ pred0,
                  const float* __restrict__ pred1,
                  const float* __restrict__ gt,
                  int nbatch) {
    // Double-buffered stage: 2 x (1K + 1K + 2K) = 8 KB
    __shared__ __align__(16) u64 sp0[2][PNUM];
    __shared__ __align__(16) u64 sp1[2][PNUM];
    __shared__ __align__(16) u64 sng[2][2 * PNUM];  // raw gt, duplicated ring
    __shared__ float redA[4], redB[4];

    const int tid = threadIdx.x;
    const int blk = blockIdx.x;
    const int b0 = blk * NB;

    int nb_local = nbatch - b0;
    if (nb_local > NB) nb_local = NB;

    // Stage batch 0 via cp.async (no registers consumed).
    {
        const int g0 = b0 * PNUM + tid;
        cpa8(__cvta_generic_to_shared(&sp0[0][tid]), pred0 + 2 * g0);
        cpa8(__cvta_generic_to_shared(&sp1[0][tid]), pred1 + 2 * g0);
        cpa8(__cvta_generic_to_shared(&sng[0][tid]), gt + 2 * g0);
        cpa8(__cvta_generic_to_shared(&sng[0][tid + PNUM]), gt + 2 * g0);
    }
    cpa_commit();

    float blocksum = 0.0f;

    for (int t = 0; t < nb_local; t++) {
        const int buf = t & 1;

        // Prefetch batch t+1 into the other buffer (WAR-safe: previous
        // iteration's epilogue __syncthreads ordered all reads of it).
        if (t + 1 < nb_local) {
            const int gn = (b0 + t + 1) * PNUM + tid;
            const int nbuf = buf ^ 1;
            cpa8(__cvta_generic_to_shared(&sp0[nbuf][tid]), pred0 + 2 * gn);
            cpa8(__cvta_generic_to_shared(&sp1[nbuf][tid]), pred1 + 2 * gn);
            cpa8(__cvta_generic_to_shared(&sng[nbuf][tid]), gt + 2 * gn);
            cpa8(__cvta_generic_to_shared(&sng[nbuf][tid + PNUM]), gt + 2 * gn);
        }
        cpa_commit();      // committed even when empty: keeps group counting uniform
        cpa_wait1();       // batch t's group is now complete
        __syncthreads();

        // Thread tid handles shift j = tid for both preds.
        const u64* gbase = &sng[buf][tid];
        u64 sQ0 = 0ull, sM20 = 0ull, sM0 = 0ull;
        u64 sQ1 = 0ull, sM21 = 0ull, sM1 = 0ull;

#pragma unroll 16
        for (int i = 0; i < PNUM; i += 2) {
            ulonglong2 P0 = *reinterpret_cast<const ulonglong2*>(&sp0[buf][i]);  // LDS.128 bcast
            ulonglong2 P1 = *reinterpret_cast<const ulonglong2*>(&sp1[buf][i]);  // LDS.128 bcast
            u64 ga = gbase[i];       // LDS.64 conflict-free
            u64 gb = gbase[i + 1];
            evalpair(P0.x, ga, sQ0, sM20, sM0);
            evalpair(P0.y, gb, sQ0, sM20, sM0);
            evalpair(P1.x, ga, sQ1, sM21, sM1);
            evalpair(P1.y, gb, sQ1, sM21, sM1);
        }

        // constant term: 256 pair-terms * (-0.5) = -128 per shift
        float qx, qy, m2x, m2y, mx, my;
        pk_unpack(sQ0, qx, qy);
        pk_unpack(sM20, m2x, m2y);
        pk_unpack(sM0, mx, my);
        float dis0 = (0.5f * ((qx + qy) - (m2x + m2y)) + (mx + my) - 128.0f) * (1.0f / PNUM);
        pk_unpack(sQ1, qx, qy);
        pk_unpack(sM21, m2x, m2y);
        pk_unpack(sM1, mx, my);
        float dis1 = (0.5f * ((qx + qy) - (m2x + m2y)) + (mx + my) - 128.0f) * (1.0f / PNUM);

        // min over 128 shifts: warp shfl min, then 4 warp partials.
#pragma unroll
        for (int o = 16; o > 0; o >>= 1) {
            dis0 = fminf(dis0, __shfl_xor_sync(0xffffffffu, dis0, o));
            dis1 = fminf(dis1, __shfl_xor_sync(0xffffffffu, dis1, o));
        }
        const int w = tid >> 5;
        if ((tid & 31) == 0) {
            redA[w] = dis0;
            redB[w] = dis1;
        }
        __syncthreads();  // publishes red*, and fences buffer reuse
        if (tid == 0) {
            float m0 = fminf(fminf(redA[0], redA[1]), fminf(redA[2], redA[3]));
            float m1 = fminf(fminf(redB[0], redB[1]), fminf(redB[2], redB[3]));
            blocksum += m0 + m1;
        }
    }

    if (tid == 0)
        g_block_loss[blk] = blocksum;
}

__global__ void reduce_kernel(float* __restrict__ out, int nbatch, int nblocks) {
    __shared__ float sred[16];
    const int tid = threadIdx.x;
    float acc = 0.0f;
    for (int i = tid; i < nblocks; i += 512)
        acc += g_block_loss[i];
#pragma unroll
    for (int o = 16; o > 0; o >>= 1)
        acc += __shfl_xor_sync(0xffffffffu, acc, o);
    if ((tid & 31) == 0) sred[tid >> 5] = acc;
    __syncthreads();
    if (tid < 32) {
        float v = (tid < 16) ? sred[tid] : 0.0f;
#pragma unroll
        for (int o = 8; o > 0; o >>= 1)
            v += __shfl_xor_sync(0xffffffffu, v, o);
        if (tid == 0) out[0] = v * (0.5f / (float)nbatch);
    }
}

extern "C" void kernel_launch(void* const* d_in, const int* in_sizes, int n_in,
                              void* d_out, int out_size) {
    const float* pred0 = (const float*)d_in[0];
    const float* pred1 = (const float*)d_in[1];
    const float* gt    = (const float*)d_in[2];
    int nbatch = in_sizes[0] / (PNUM * 2);
    if (nbatch > MAXBATCH) nbatch = MAXBATCH;
    int nblocks = (nbatch + NB - 1) / NB;

    match_kernel<<<nblocks, PNUM>>>(pred0, pred1, gt, nbatch);
    reduce_kernel<<<1, 512>>>((float*)d_out, nbatch, nblocks);
}